// round 2
// baseline (speedup 1.0000x reference)
#include <cuda_runtime.h>
#include <cstdint>

#define HID 128
#define ENC_T 8192
#define DEC_T 4096
#define CLUSTER 4
#define TPB 128   // 4 warps: one gate-row per thread (4 gates x 32 units)

__device__ __forceinline__ uint32_t smem_u32(const void* p) {
    return (uint32_t)__cvta_generic_to_shared(p);
}

__device__ __forceinline__ void st_cluster_f32(uint32_t laddr, uint32_t rank, float v) {
    uint32_t raddr;
    asm volatile("mapa.shared::cluster.u32 %0, %1, %2;"
                 : "=r"(raddr) : "r"(laddr), "r"(rank));
    asm volatile("st.shared::cluster.f32 [%0], %1;"
                 :: "r"(raddr), "f"(v) : "memory");
}

__device__ __forceinline__ void cluster_sync() {
    asm volatile("barrier.cluster.arrive.aligned;" ::: "memory");
    asm volatile("barrier.cluster.wait.aligned;" ::: "memory");
}

__device__ __forceinline__ float sigm_(float x) {
    return 1.0f / (1.0f + __expf(-x));
}
__device__ __forceinline__ float tanh_(float x) {
    // tanh(x) = 1 - 2/(exp(2x)+1); handles +-inf saturation correctly
    return 1.0f - 2.0f / (__expf(2.0f * x) + 1.0f);
}

__global__ void __cluster_dims__(CLUSTER, 1, 1) __launch_bounds__(TPB, 1)
seq2seq_kernel(const float* __restrict__ input_seq,
               const float* __restrict__ enc_Wih, const float* __restrict__ enc_Whh,
               const float* __restrict__ enc_bih, const float* __restrict__ enc_bhh,
               const float* __restrict__ dec_Wih, const float* __restrict__ dec_Whh,
               const float* __restrict__ dec_bih, const float* __restrict__ dec_bhh,
               const float* __restrict__ fc_W,    const float* __restrict__ fc_b,
               float* __restrict__ out)
{
    __shared__ float xs[ENC_T];          // 32 KB: whole input sequence
    __shared__ __align__(16) float hbuf[2][HID];  // double-buffered h (full 128, all CTAs identical)
    __shared__ float gates_sm[4 * 32];   // pre-activations [gate][unit-local]
    __shared__ float fcW_sm[HID];
    __shared__ float pred_sm;

    const int tid  = threadIdx.x;
    uint32_t rank;
    asm("mov.u32 %0, %%cluster_ctarank;" : "=r"(rank));
    const int gate = tid >> 5;            // 0..3 : i, f, g, o
    const int lane = tid & 31;            // unit within this CTA's 32
    const int unit = (int)rank * 32 + lane;      // global hidden unit this CTA owns (warp0)
    const int row  = gate * HID + (int)rank * 32 + lane;  // this thread's gate row in [0,512)

    // Stage input sequence + fc weights into SMEM; init h double-buffer
    for (int i = tid; i < ENC_T; i += TPB) xs[i] = input_seq[i];
    if (tid < HID) { fcW_sm[tid] = fc_W[tid]; hbuf[0][tid] = 0.0f; hbuf[1][tid] = 0.0f; }
    const float fcb = fc_b[0];

    // Encoder weights -> registers
    float w[HID];
    #pragma unroll
    for (int k = 0; k < HID; k++) w[k] = enc_Whh[row * HID + k];
    float btot = enc_bih[row] + enc_bhh[row];
    float wih  = enc_Wih[row];

    float c = 0.0f;   // cell state: valid in warp 0 (lane == local unit)

    __syncthreads();
    cluster_sync();

    // ---------------- encoder: 8192 steps ----------------
    #pragma unroll 1
    for (int t = 0; t < ENC_T; ++t) {
        const int p = t & 1;
        const float x = xs[t];
        float acc = fmaf(wih, x, btot);
        const float4* h4 = (const float4*)hbuf[p];
        #pragma unroll
        for (int j = 0; j < HID / 4; j++) {
            float4 hv = h4[j];
            acc = fmaf(w[4*j+0], hv.x, acc);
            acc = fmaf(w[4*j+1], hv.y, acc);
            acc = fmaf(w[4*j+2], hv.z, acc);
            acc = fmaf(w[4*j+3], hv.w, acc);
        }
        gates_sm[gate * 32 + lane] = acc;
        __syncthreads();
        if (tid < 32) {
            const float gi = gates_sm[lane];
            const float gf = gates_sm[32 + lane];
            const float gg = gates_sm[64 + lane];
            const float go = gates_sm[96 + lane];
            c = sigm_(gf) * c + sigm_(gi) * tanh_(gg);
            const float hn = sigm_(go) * tanh_(c);
            const uint32_t laddr = smem_u32(&hbuf[p ^ 1][unit]);
            #pragma unroll
            for (int r = 0; r < CLUSTER; r++) st_cluster_f32(laddr, (uint32_t)r, hn);
        }
        cluster_sync();   // release DSMEM stores; acquire peers' h
    }

    // Decoder weights -> same registers
    #pragma unroll
    for (int k = 0; k < HID; k++) w[k] = dec_Whh[row * HID + k];
    btot = dec_bih[row] + dec_bhh[row];
    wih  = dec_Wih[row];

    float y = 0.0f;  // decoder feedback, uniform across all threads/CTAs

    // ---------------- decoder: 4096 steps ----------------
    #pragma unroll 1
    for (int t = 0; t < DEC_T; ++t) {
        const int p = t & 1;   // ENC_T even, so parity continues cleanly: h lives in hbuf[0] at t=0
        float acc = fmaf(wih, y, btot);
        const float4* h4 = (const float4*)hbuf[p];
        #pragma unroll
        for (int j = 0; j < HID / 4; j++) {
            float4 hv = h4[j];
            acc = fmaf(w[4*j+0], hv.x, acc);
            acc = fmaf(w[4*j+1], hv.y, acc);
            acc = fmaf(w[4*j+2], hv.z, acc);
            acc = fmaf(w[4*j+3], hv.w, acc);
        }
        gates_sm[gate * 32 + lane] = acc;
        __syncthreads();
        if (tid < 32) {
            const float gi = gates_sm[lane];
            const float gf = gates_sm[32 + lane];
            const float gg = gates_sm[64 + lane];
            const float go = gates_sm[96 + lane];
            c = sigm_(gf) * c + sigm_(gi) * tanh_(gg);
            const float hn = sigm_(go) * tanh_(c);
            const uint32_t laddr = smem_u32(&hbuf[p ^ 1][unit]);
            #pragma unroll
            for (int r = 0; r < CLUSTER; r++) st_cluster_f32(laddr, (uint32_t)r, hn);
        }
        cluster_sync();

        // pred = fc_W @ h_new + fc_b, computed redundantly in every CTA (avoids 2nd cluster sync)
        if (tid < 32) {
            const float* hn = hbuf[p ^ 1];
            float s = fcW_sm[lane]      * hn[lane]
                    + fcW_sm[lane + 32] * hn[lane + 32]
                    + fcW_sm[lane + 64] * hn[lane + 64]
                    + fcW_sm[lane + 96] * hn[lane + 96];
            #pragma unroll
            for (int o = 16; o > 0; o >>= 1) s += __shfl_xor_sync(0xffffffffu, s, o);
            if (lane == 0) {
                const float pred = s + fcb;
                pred_sm = pred;
                if (rank == 0) out[t] = pred;
            }
        }
        __syncthreads();
        y = pred_sm;
    }
}

extern "C" void kernel_launch(void* const* d_in, const int* in_sizes, int n_in,
                              void* d_out, int out_size) {
    (void)in_sizes; (void)n_in; (void)out_size;
    seq2seq_kernel<<<CLUSTER, TPB>>>(
        (const float*)d_in[0],
        (const float*)d_in[1], (const float*)d_in[2],
        (const float*)d_in[3], (const float*)d_in[4],
        (const float*)d_in[5], (const float*)d_in[6],
        (const float*)d_in[7], (const float*)d_in[8],
        (const float*)d_in[9], (const float*)d_in[10],
        (float*)d_out);
}

// round 3
// speedup vs baseline: 1.2822x; 1.2822x over previous
#include <cuda_runtime.h>
#include <cstdint>

#define HID 128
#define ENC_T 8192
#define DEC_T 4096
#define CLUSTER 4
#define TPB 128   // 128 threads: lane = (unit 0..31)<<2 | (gate 0..3)

__device__ __forceinline__ uint32_t smem_u32(const void* p) {
    return (uint32_t)__cvta_generic_to_shared(p);
}

__device__ __forceinline__ void st_cluster_f32(uint32_t laddr, uint32_t rank, float v) {
    uint32_t raddr;
    asm volatile("mapa.shared::cluster.u32 %0, %1, %2;"
                 : "=r"(raddr) : "r"(laddr), "r"(rank));
    asm volatile("st.shared::cluster.f32 [%0], %1;"
                 :: "r"(raddr), "f"(v) : "memory");
}

__device__ __forceinline__ void cluster_sync() {
    asm volatile("barrier.cluster.arrive.aligned;" ::: "memory");
    asm volatile("barrier.cluster.wait.aligned;" ::: "memory");
}

__device__ __forceinline__ float sigm_(float x) { return 1.0f / (1.0f + __expf(-x)); }
__device__ __forceinline__ float tanh_(float x) { return 1.0f - 2.0f / (__expf(2.0f * x) + 1.0f); }

// 128-term dot: per-lane weights in packed f32x2 registers vs broadcast h in SMEM.
// 4 rotating packed accumulators -> dep chain 16*4=64cyc, issue ~128cyc.
__device__ __forceinline__ float dot128(const unsigned long long* w2, uint32_t haddr) {
    unsigned long long a0 = 0ull, a1 = 0ull, a2 = 0ull, a3 = 0ull;
    #pragma unroll
    for (int j = 0; j < 16; j++) {
        unsigned long long h01, h23, h45, h67;
        asm volatile("ld.shared.v2.b64 {%0,%1},[%2];"
                     : "=l"(h01), "=l"(h23) : "r"(haddr + j * 32));
        asm volatile("ld.shared.v2.b64 {%0,%1},[%2];"
                     : "=l"(h45), "=l"(h67) : "r"(haddr + j * 32 + 16));
        asm("fma.rn.f32x2 %0,%1,%2,%0;" : "+l"(a0) : "l"(w2[4 * j + 0]), "l"(h01));
        asm("fma.rn.f32x2 %0,%1,%2,%0;" : "+l"(a1) : "l"(w2[4 * j + 1]), "l"(h23));
        asm("fma.rn.f32x2 %0,%1,%2,%0;" : "+l"(a2) : "l"(w2[4 * j + 2]), "l"(h45));
        asm("fma.rn.f32x2 %0,%1,%2,%0;" : "+l"(a3) : "l"(w2[4 * j + 3]), "l"(h67));
    }
    asm("add.rn.f32x2 %0,%0,%1;" : "+l"(a0) : "l"(a2));
    asm("add.rn.f32x2 %0,%0,%1;" : "+l"(a1) : "l"(a3));
    asm("add.rn.f32x2 %0,%0,%1;" : "+l"(a0) : "l"(a1));
    float lo, hi;
    asm("mov.b64 {%0,%1},%2;" : "=f"(lo), "=f"(hi) : "l"(a0));
    return lo + hi;
}

__device__ __forceinline__ void load_weights(const float* __restrict__ Whh, int row,
                                             unsigned long long* w2) {
    #pragma unroll
    for (int j = 0; j < 64; j++) {
        float a = Whh[row * HID + 2 * j];
        float b = Whh[row * HID + 2 * j + 1];
        asm("mov.b64 %0,{%1,%2};" : "=l"(w2[j]) : "f"(a), "f"(b));
    }
}

__global__ void __cluster_dims__(CLUSTER, 1, 1) __launch_bounds__(TPB, 1)
seq2seq_kernel(const float* __restrict__ input_seq,
               const float* __restrict__ enc_Wih, const float* __restrict__ enc_Whh,
               const float* __restrict__ enc_bih, const float* __restrict__ enc_bhh,
               const float* __restrict__ dec_Wih, const float* __restrict__ dec_Whh,
               const float* __restrict__ dec_bih, const float* __restrict__ dec_bhh,
               const float* __restrict__ fc_W,    const float* __restrict__ fc_b,
               float* __restrict__ out)
{
    __shared__ float xs[ENC_T];                       // 32 KB input sequence
    __shared__ __align__(16) float hbuf[2][HID];      // double-buffered h (replicated per CTA)
    __shared__ __align__(16) float fcpart[2][16];     // double-buffered fc partials (4 CTAs x 4 warps)

    const int tid  = threadIdx.x;
    uint32_t rank;
    asm("mov.u32 %0, %%cluster_ctarank;" : "=r"(rank));
    const int unit  = tid >> 2;                 // local unit 0..31
    const int gate  = tid & 3;                  // i,f,g,o
    const int gunit = (int)rank * 32 + unit;    // global unit this lane-group owns
    const int row   = gate * HID + gunit;       // row in [0,512)
    const int wid   = tid >> 5;
    const int lane  = tid & 31;

    for (int i = tid; i < ENC_T; i += TPB) xs[i] = input_seq[i];
    if (tid < HID) { hbuf[0][tid] = 0.0f; hbuf[1][tid] = 0.0f; }
    if (tid < 32)  { fcpart[0][tid & 15] = 0.0f; fcpart[1][tid & 15] = 0.0f; }

    const float fcb = fc_b[0];
    const float fcw = fc_W[gunit];

    unsigned long long w2[64];                  // 128 packed weights (this lane's row)
    load_weights(enc_Whh, row, w2);
    float btot = enc_bih[row] + enc_bhh[row];
    float wihr = enc_Wih[row];

    float c = 0.0f;                             // cell state, kept redundantly in all 4 gate lanes
    const uint32_t hb0 = smem_u32(hbuf[0]);
    const uint32_t hb1 = smem_u32(hbuf[1]);
    const uint32_t hdst_local = gunit * 4;      // byte offset of this unit's slot within hbuf row
    const unsigned FULL = 0xffffffffu;
    const int base = lane & ~3;

    __syncthreads();
    cluster_sync();

    // ---------------- encoder: 8192 steps ----------------
    #pragma unroll 1
    for (int t = 0; t < ENC_T; ++t) {
        const uint32_t hsrc = (t & 1) ? hb1 : hb0;
        const uint32_t hdst = ((t & 1) ? hb0 : hb1) + hdst_local;

        float acc = dot128(w2, hsrc);
        acc += fmaf(wihr, xs[t], btot);

        // activate own gate, then exchange activated gates within the 4-lane group
        const float a  = (gate == 2) ? tanh_(acc) : sigm_(acc);
        const float gi = __shfl_sync(FULL, a, base + 0);
        const float gf = __shfl_sync(FULL, a, base + 1);
        const float gg = __shfl_sync(FULL, a, base + 2);
        const float go = __shfl_sync(FULL, a, base + 3);

        c = gf * c + gi * gg;
        const float hn = go * tanh_(c);

        // lane with gate==r delivers this unit's h to CTA r (incl. self)
        st_cluster_f32(hdst, (uint32_t)gate, hn);
        cluster_sync();
    }

    // ---------------- decoder weights ----------------
    load_weights(dec_Whh, row, w2);
    btot = dec_bih[row] + dec_bhh[row];
    wihr = dec_Wih[row];

    const uint32_t fp0 = smem_u32(fcpart[0]);
    const uint32_t fp1 = smem_u32(fcpart[1]);

    // ---------------- decoder: 4096 steps ----------------
    // ENC_T is even so parity continues: t=0 reads hbuf[0].
    #pragma unroll 1
    for (int t = 0; t < DEC_T; ++t) {
        const int p = t & 1;
        const uint32_t hsrc = p ? hb1 : hb0;
        const uint32_t hdst = (p ? hb0 : hb1) + hdst_local;

        float acc = dot128(w2, hsrc);

        // y = fc_W @ h_prev + fc_b, reduced from 16 per-warp partials (identical
        // order in every CTA -> bit-identical y everywhere). Overlaps the dot.
        float y;
        if (t == 0) {
            y = 0.0f;
        } else {
            const float* fp = fcpart[p];
            float4 p0 = *(const float4*)&fp[0];
            float4 p1 = *(const float4*)&fp[4];
            float4 p2 = *(const float4*)&fp[8];
            float4 p3 = *(const float4*)&fp[12];
            float s01 = ((p0.x + p0.y) + (p0.z + p0.w)) + ((p1.x + p1.y) + (p1.z + p1.w));
            float s23 = ((p2.x + p2.y) + (p2.z + p2.w)) + ((p3.x + p3.y) + (p3.z + p3.w));
            y = (s01 + s23) + fcb;
            if (rank == 0 && tid == 0) out[t - 1] = y;   // pred of previous step
        }

        acc += fmaf(wihr, y, btot);

        const float a  = (gate == 2) ? tanh_(acc) : sigm_(acc);
        const float gi = __shfl_sync(FULL, a, base + 0);
        const float gf = __shfl_sync(FULL, a, base + 1);
        const float gg = __shfl_sync(FULL, a, base + 2);
        const float go = __shfl_sync(FULL, a, base + 3);

        c = gf * c + gi * gg;
        const float hn = go * tanh_(c);

        st_cluster_f32(hdst, (uint32_t)gate, hn);

        // fc partial over this CTA's 32 units: reduce fcw*hn across the 8
        // unit-groups of each warp (xor 4/8/16 stays within gate-class).
        float v = fcw * hn;
        v += __shfl_xor_sync(FULL, v, 4);
        v += __shfl_xor_sync(FULL, v, 8);
        v += __shfl_xor_sync(FULL, v, 16);
        if (lane == 0) {
            const uint32_t pa = (p ? fp0 : fp1) + ((int)rank * 4 + wid) * 4;
            #pragma unroll
            for (int r = 0; r < CLUSTER; r++) st_cluster_f32(pa, (uint32_t)r, v);
        }
        cluster_sync();
    }

    // final prediction (partials of last step live in fcpart[((DEC_T-1)&1)^1] = fcpart[0])
    if (rank == 0 && tid == 0) {
        const float* fp = fcpart[0];
        float4 p0 = *(const float4*)&fp[0];
        float4 p1 = *(const float4*)&fp[4];
        float4 p2 = *(const float4*)&fp[8];
        float4 p3 = *(const float4*)&fp[12];
        float s01 = ((p0.x + p0.y) + (p0.z + p0.w)) + ((p1.x + p1.y) + (p1.z + p1.w));
        float s23 = ((p2.x + p2.y) + (p2.z + p2.w)) + ((p3.x + p3.y) + (p3.z + p3.w));
        out[DEC_T - 1] = (s01 + s23) + fcb;
    }
}

extern "C" void kernel_launch(void* const* d_in, const int* in_sizes, int n_in,
                              void* d_out, int out_size) {
    (void)in_sizes; (void)n_in; (void)out_size;
    seq2seq_kernel<<<CLUSTER, TPB>>>(
        (const float*)d_in[0],
        (const float*)d_in[1], (const float*)d_in[2],
        (const float*)d_in[3], (const float*)d_in[4],
        (const float*)d_in[5], (const float*)d_in[6],
        (const float*)d_in[7], (const float*)d_in[8],
        (const float*)d_in[9], (const float*)d_in[10],
        (float*)d_out);
}

// round 6
// speedup vs baseline: 1.5117x; 1.1790x over previous
#include <cuda_runtime.h>
#include <cstdint>

#define HID 128
#define ENC_T 8192
#define DEC_T 4096
#define CLUSTER 4
#define TPB 128   // lane = (unit 0..31)<<2 | (gate 0..3)

__device__ __forceinline__ uint32_t smem_u32(const void* p) {
    return (uint32_t)__cvta_generic_to_shared(p);
}

__device__ __forceinline__ uint32_t mapa_(uint32_t laddr, uint32_t rank) {
    uint32_t r;
    asm("mapa.shared::cluster.u32 %0, %1, %2;" : "=r"(r) : "r"(laddr), "r"(rank));
    return r;
}

__device__ __forceinline__ float sigm_(float x) { return 1.0f / (1.0f + __expf(-x)); }
__device__ __forceinline__ float tanh_(float x) { return 1.0f - 2.0f / (__expf(2.0f * x) + 1.0f); }

// 128-term dot: per-lane packed-f32x2 weights vs broadcast h in SMEM.
__device__ __forceinline__ float dot128(const unsigned long long* w2, uint32_t haddr) {
    unsigned long long a0 = 0ull, a1 = 0ull, a2 = 0ull, a3 = 0ull;
    #pragma unroll
    for (int j = 0; j < 16; j++) {
        unsigned long long h01, h23, h45, h67;
        asm volatile("ld.shared.v2.b64 {%0,%1},[%2];"
                     : "=l"(h01), "=l"(h23) : "r"(haddr + j * 32));
        asm volatile("ld.shared.v2.b64 {%0,%1},[%2];"
                     : "=l"(h45), "=l"(h67) : "r"(haddr + j * 32 + 16));
        asm("fma.rn.f32x2 %0,%1,%2,%0;" : "+l"(a0) : "l"(w2[4 * j + 0]), "l"(h01));
        asm("fma.rn.f32x2 %0,%1,%2,%0;" : "+l"(a1) : "l"(w2[4 * j + 1]), "l"(h23));
        asm("fma.rn.f32x2 %0,%1,%2,%0;" : "+l"(a2) : "l"(w2[4 * j + 2]), "l"(h45));
        asm("fma.rn.f32x2 %0,%1,%2,%0;" : "+l"(a3) : "l"(w2[4 * j + 3]), "l"(h67));
    }
    asm("add.rn.f32x2 %0,%0,%1;" : "+l"(a0) : "l"(a2));
    asm("add.rn.f32x2 %0,%0,%1;" : "+l"(a1) : "l"(a3));
    asm("add.rn.f32x2 %0,%0,%1;" : "+l"(a0) : "l"(a1));
    float lo, hi;
    asm("mov.b64 {%0,%1},%2;" : "=f"(lo), "=f"(hi) : "l"(a0));
    return lo + hi;
}

__global__ void __cluster_dims__(CLUSTER, 1, 1) __launch_bounds__(TPB, 1)
seq2seq_kernel(const float* __restrict__ input_seq,
               const float* __restrict__ enc_Wih, const float* __restrict__ enc_Whh,
               const float* __restrict__ enc_bih, const float* __restrict__ enc_bhh,
               const float* __restrict__ dec_Wih, const float* __restrict__ dec_Whh,
               const float* __restrict__ dec_bih, const float* __restrict__ dec_bhh,
               const float* __restrict__ fc_W,    const float* __restrict__ fc_b,
               float* __restrict__ out)
{
    __shared__ float xs[ENC_T];                               // 32 KB input sequence
    __shared__ __align__(16) float hbuf[2][HID];              // local contiguous h copy (per parity)
    __shared__ __align__(16) unsigned long long pkbuf[2][HID];// {h:f32, tag:s32} delivery slots
    __shared__ float fcW_sm[HID];
    __shared__ float qpart[4];

    const int tid  = threadIdx.x;
    uint32_t rank;
    asm("mov.u32 %0, %%cluster_ctarank;" : "=r"(rank));
    const int unit  = tid >> 2;
    const int gate  = tid & 3;                 // i,f,g,o ; also = delivery-target CTA
    const int gunit = (int)rank * 32 + unit;   // global unit this lane-group owns
    const int row   = gate * HID + gunit;
    const int wid   = tid >> 5;
    const int lane  = tid & 31;
    const unsigned FULL = 0xffffffffu;
    const int base = lane & ~3;

    for (int i = tid; i < ENC_T; i += TPB) xs[i] = input_seq[i];
    if (tid < HID) { fcW_sm[tid] = fc_W[tid]; pkbuf[0][tid] = 0ull; pkbuf[1][tid] = 0ull; }
    const float fcb = fc_b[0];

    // hoisted addresses
    const uint32_t hb[2]   = { smem_u32(hbuf[0]), smem_u32(hbuf[1]) };
    const uint32_t pkb[2]  = { smem_u32(pkbuf[0]), smem_u32(pkbuf[1]) };
    const uint32_t slot[2] = { pkb[0] + tid * 8, pkb[1] + tid * 8 };   // my poll slot (unit = tid)
    const uint32_t hloc[2] = { hb[0] + tid * 4, hb[1] + tid * 4 };
    const uint32_t rpk[2]  = { mapa_(pkb[0] + gunit * 8, (uint32_t)gate),
                               mapa_(pkb[1] + gunit * 8, (uint32_t)gate) };

    unsigned long long w2[64];                 // this lane's 128 weights, packed f32x2
    #pragma unroll
    for (int j = 0; j < 64; j++) {
        float a = enc_Whh[row * HID + 2 * j];
        float b = enc_Whh[row * HID + 2 * j + 1];
        asm("mov.b64 %0,{%1,%2};" : "=l"(w2[j]) : "f"(a), "f"(b));
    }
    float btot = enc_bih[row] + enc_bhh[row];
    float wihr = enc_Wih[row];

    float c = 0.0f;                            // cell state (replicated in the 4 gate lanes)

    __syncthreads();
    asm volatile("barrier.cluster.arrive.aligned;" ::: "memory");
    asm volatile("barrier.cluster.wait.aligned;"   ::: "memory");

    // ---------------- encoder: steps s = 0 .. ENC_T-1 ----------------
    #pragma unroll 1
    for (int s = 0; s < ENC_T; ++s) {
        const int p = s & 1, np = p ^ 1;
        const float ai = fmaf(wihr, xs[s], btot);

        // single-8B-atomic handshake: tag==s implies h(s) is in the same word
        uint32_t hv; int tg;
        do {
            asm volatile("ld.volatile.shared.v2.b32 {%0,%1},[%2];"
                         : "=r"(hv), "=r"(tg) : "r"(slot[p]));
        } while (tg != s);
        asm volatile("st.shared.b32 [%0],%1;" :: "r"(hloc[p]), "r"(hv) : "memory");
        __syncthreads();                       // drains STS; all 128 h gathered

        float acc = dot128(w2, hb[p]) + ai;
        const float a  = (gate == 2) ? tanh_(acc) : sigm_(acc);
        const float gi = __shfl_sync(FULL, a, base + 0);
        const float gf = __shfl_sync(FULL, a, base + 1);
        const float gg = __shfl_sync(FULL, a, base + 2);
        const float go = __shfl_sync(FULL, a, base + 3);
        c = gf * c + gi * gg;
        const float hn = go * tanh_(c);

        unsigned long long pkt;
        asm("mov.b64 %0,{%1,%2};" : "=l"(pkt) : "f"(hn), "r"(s + 1));
        asm volatile("st.shared::cluster.b64 [%0],%1;" :: "r"(rpk[np]), "l"(pkt) : "memory");
    }

    // ---------------- decoder weights: fold fc_W/fc_b into Whh/bias ----------------
    // W.h + wih*(fcW.h + fcb) + b == (W + wih*fcW^T).h + (b + wih*fcb)
    wihr = dec_Wih[row];
    #pragma unroll
    for (int j = 0; j < 64; j++) {
        float a = fmaf(wihr, fcW_sm[2 * j],     dec_Whh[row * HID + 2 * j]);
        float b = fmaf(wihr, fcW_sm[2 * j + 1], dec_Whh[row * HID + 2 * j + 1]);
        asm("mov.b64 %0,{%1,%2};" : "=l"(w2[j]) : "f"(a), "f"(b));
    }
    const float btot_pl   = dec_bih[row] + dec_bhh[row];
    const float btot_fold = fmaf(wihr, fcb, btot_pl);

    // fc weights for the out-emitter (rank0 warp0); harmless elsewhere
    const float f0 = fcW_sm[lane], f1 = fcW_sm[lane + 32],
                f2 = fcW_sm[lane + 64], f3 = fcW_sm[lane + 96];
    const bool emitter = (rank == 0) && (wid == 0);

    // ---------------- decoder: steps s = ENC_T .. ENC_T+DEC_T-1 ----------------
    #pragma unroll 1
    for (int d = 0; d < DEC_T; ++d) {
        const int s = ENC_T + d;
        const int p = s & 1, np = p ^ 1;

        uint32_t hv; int tg;
        do {
            asm volatile("ld.volatile.shared.v2.b32 {%0,%1},[%2];"
                         : "=r"(hv), "=r"(tg) : "r"(slot[p]));
        } while (tg != s);
        asm volatile("st.shared.b32 [%0],%1;" :: "r"(hloc[p]), "r"(hv) : "memory");
        __syncthreads();

        float ai;
        if (d == 0) {
            // first step must see y = 0: subtract the folded-in fcW.h_enc term
            float pq = fcW_sm[tid] * hbuf[p][tid];
            #pragma unroll
            for (int o = 1; o < 32; o <<= 1) pq += __shfl_xor_sync(FULL, pq, o);
            if (lane == 0) qpart[wid] = pq;
            __syncthreads();
            const float q = (qpart[0] + qpart[1]) + (qpart[2] + qpart[3]);
            ai = btot_pl - wihr * q;
        } else {
            ai = btot_fold;
        }

        float acc = dot128(w2, hb[p]) + ai;
        const float a  = (gate == 2) ? tanh_(acc) : sigm_(acc);
        const float gi = __shfl_sync(FULL, a, base + 0);
        const float gf = __shfl_sync(FULL, a, base + 1);
        const float gg = __shfl_sync(FULL, a, base + 2);
        const float go = __shfl_sync(FULL, a, base + 3);
        c = gf * c + gi * gg;
        const float hn = go * tanh_(c);

        unsigned long long pkt;
        asm("mov.b64 %0,{%1,%2};" : "=l"(pkt) : "f"(hn), "r"(s + 1));
        asm volatile("st.shared::cluster.b64 [%0],%1;" :: "r"(rpk[np]), "l"(pkt) : "memory");

        // off-critical-path: pred_{d-1} = fcW . h_d + fcb  (full 128 units, local copy)
        if (emitter && d >= 1) {
            float v = f0 * hbuf[p][lane] + f1 * hbuf[p][lane + 32]
                    + f2 * hbuf[p][lane + 64] + f3 * hbuf[p][lane + 96];
            #pragma unroll
            for (int o = 16; o > 0; o >>= 1) v += __shfl_xor_sync(FULL, v, o);
            if (lane == 0) out[d - 1] = v + fcb;
        }
    }

    // final prediction: h(ENC_T+DEC_T) sits in parity-0 slots with tag ENC_T+DEC_T
    if (rank == 0) {
        uint32_t hv; int tg;
        do {
            asm volatile("ld.volatile.shared.v2.b32 {%0,%1},[%2];"
                         : "=r"(hv), "=r"(tg) : "r"(slot[0]));
        } while (tg != ENC_T + DEC_T);
        asm volatile("st.shared.b32 [%0],%1;" :: "r"(hloc[0]), "r"(hv) : "memory");
        __syncthreads();
        if (wid == 0) {
            float v = f0 * hbuf[0][lane] + f1 * hbuf[0][lane + 32]
                    + f2 * hbuf[0][lane + 64] + f3 * hbuf[0][lane + 96];
            #pragma unroll
            for (int o = 16; o > 0; o >>= 1) v += __shfl_xor_sync(FULL, v, o);
            if (lane == 0) out[DEC_T - 1] = v + fcb;
        }
    }

    // CRITICAL: no CTA may exit while peers might still issue remote stores into
    // its SMEM (final-iteration deliveries target ALL CTAs). This barrier is the
    // R4/R5 crash fix — it keeps every CTA alive until all remote stores landed.
    asm volatile("barrier.cluster.arrive.aligned;" ::: "memory");
    asm volatile("barrier.cluster.wait.aligned;"   ::: "memory");
}

extern "C" void kernel_launch(void* const* d_in, const int* in_sizes, int n_in,
                              void* d_out, int out_size) {
    (void)in_sizes; (void)n_in; (void)out_size;
    seq2seq_kernel<<<CLUSTER, TPB>>>(
        (const float*)d_in[0],
        (const float*)d_in[1], (const float*)d_in[2],
        (const float*)d_in[3], (const float*)d_in[4],
        (const float*)d_in[5], (const float*)d_in[6],
        (const float*)d_in[7], (const float*)d_in[8],
        (const float*)d_in[9], (const float*)d_in[10],
        (float*)d_out);
}